// round 9
// baseline (speedup 1.0000x reference)
#include <cuda_runtime.h>
#include <cuda_bf16.h>
#include <cstdint>

// Problem dims
#define B_ 32
#define T_ 2048
#define C_ 384
#define H_ 64
#define NTILE 16            // T / 128 tiles

// bf16 tile images, all [128 rows][64 data + 8 pad bf16] = 144B rows
#define QK_ROWB 144
#define QK_TILE (128 * QK_ROWB)   // 18432 B

__device__ __align__(16) unsigned char g_qh[(size_t)B_ * NTILE * QK_TILE];
__device__ __align__(16) unsigned char g_ql[(size_t)B_ * NTILE * QK_TILE];
__device__ __align__(16) unsigned char g_kh[(size_t)B_ * NTILE * QK_TILE];
__device__ __align__(16) unsigned char g_kl[(size_t)B_ * NTILE * QK_TILE];
__device__ __align__(16) unsigned char g_vh[(size_t)B_ * NTILE * QK_TILE];
__device__ __align__(16) unsigned char g_vl[(size_t)B_ * NTILE * QK_TILE];

// Fused weight images: [3 K-chunks][192 rows][128 + 8 pad bf16] split hi/lo.
// Row n: tensor = n>>6 (0=K,1=Q(x0.125),2=V), head = n&63.
#define W_ROWB   272
#define W_CHUNK  (192 * W_ROWB)   // 52224 B
__device__ __align__(16) unsigned char g_wh[3 * W_CHUNK];
__device__ __align__(16) unsigned char g_wl[3 * W_CHUNK];

// ---------------------------------------------------------------------------
// Helpers (portable PTX only: mma.sync bf16, ldmatrix, cp.async.bulk, mbarrier)
// ---------------------------------------------------------------------------
__device__ __forceinline__ uint32_t smem_u32(const void* p) {
    uint32_t a;
    asm("{ .reg .u64 t; cvta.to.shared.u64 t, %1; cvt.u32.u64 %0, t; }"
        : "=r"(a) : "l"(p));
    return a;
}

#define MBARRIER_INIT(mbar, cnt) \
    asm volatile("mbarrier.init.shared.b64 [%0], %1;" \
        :: "r"((uint32_t)(mbar)), "r"((uint32_t)(cnt)) : "memory")
#define MBARRIER_EXPECT_TX(mbar, bytes) \
    asm volatile("mbarrier.arrive.expect_tx.shared.b64 _, [%0], %1;" \
        :: "r"((uint32_t)(mbar)), "r"((uint32_t)(bytes)) : "memory")

#define MBARRIER_WAIT_PARITY(mbar, parity) do { \
    uint32_t _mb = (uint32_t)(mbar); \
    uint32_t _pa = (uint32_t)(parity); \
    uint32_t _done; \
    asm volatile("{\n\t.reg .pred p;\n\t" \
        "mbarrier.try_wait.parity.acquire.cta.shared::cta.b64 p, [%1], %2;\n\t" \
        "selp.b32 %0, 1, 0, p;\n\t}" : "=r"(_done) : "r"(_mb), "r"(_pa) : "memory"); \
    if (!_done) { \
        asm volatile("{\n\t.reg .pred P1;\n\t" \
            "WL_%=:\n\t" \
            "mbarrier.try_wait.parity.acquire.cta.shared::cta.b64 P1, [%0], %1, 0x989680;\n\t" \
            "@P1 bra.uni WD_%=;\n\t" \
            "bra.uni WL_%=;\n\t" \
            "WD_%=:\n\t}" :: "r"(_mb), "r"(_pa) : "memory"); \
    } \
} while (0)

#define BULK_G2S(dst, src, bytes, mbar) \
    asm volatile("cp.async.bulk.shared::cta.global.mbarrier::complete_tx::bytes [%0], [%1], %2, [%3];" \
        :: "r"((uint32_t)(dst)), "l"(src), "r"((uint32_t)(bytes)), "r"((uint32_t)(mbar)) : "memory")

// m16n8k16 row.col bf16 -> f32, D += A*B
__device__ __forceinline__ void mma16816(float* d, const uint32_t* a, const uint32_t* b) {
    asm volatile("mma.sync.aligned.m16n8k16.row.col.f32.bf16.bf16.f32 "
        "{%0,%1,%2,%3}, {%4,%5,%6,%7}, {%8,%9}, {%0,%1,%2,%3};"
        : "+f"(d[0]), "+f"(d[1]), "+f"(d[2]), "+f"(d[3])
        : "r"(a[0]), "r"(a[1]), "r"(a[2]), "r"(a[3]), "r"(b[0]), "r"(b[1]));
}

__device__ __forceinline__ void ldm_x4(uint32_t* r, uint32_t addr) {
    asm volatile("ldmatrix.sync.aligned.m8n8.x4.shared.b16 {%0,%1,%2,%3}, [%4];"
        : "=r"(r[0]), "=r"(r[1]), "=r"(r[2]), "=r"(r[3]) : "r"(addr));
}
__device__ __forceinline__ void ldm_x4t(uint32_t* r, uint32_t addr) {
    asm volatile("ldmatrix.sync.aligned.m8n8.x4.trans.shared.b16 {%0,%1,%2,%3}, [%4];"
        : "=r"(r[0]), "=r"(r[1]), "=r"(r[2]), "=r"(r[3]) : "r"(addr));
}

__device__ __forceinline__ void split2(float a, float b, uint32_t& hp, uint32_t& lp) {
    __nv_bfloat16 ha = __float2bfloat16_rn(a);
    __nv_bfloat16 hb = __float2bfloat16_rn(b);
    float la = a - __bfloat162float(ha);
    float lb = b - __bfloat162float(hb);
    __nv_bfloat16 hla = __float2bfloat16_rn(la);
    __nv_bfloat16 hlb = __float2bfloat16_rn(lb);
    hp = (uint32_t)reinterpret_cast<uint16_t&>(ha)
       | ((uint32_t)reinterpret_cast<uint16_t&>(hb) << 16);
    lp = (uint32_t)reinterpret_cast<uint16_t&>(hla)
       | ((uint32_t)reinterpret_cast<uint16_t&>(hlb) << 16);
}

// ---------------------------------------------------------------------------
// Kernel 0: prep fused weight images. Grid (192, 3), block 128.
// ---------------------------------------------------------------------------
__global__ void prep_w_kernel(const float* __restrict__ Wk,
                              const float* __restrict__ Wq,
                              const float* __restrict__ Wv)
{
    const int n  = blockIdx.x;           // 0..191
    const int kc = blockIdx.y;           // 0..2
    const int c  = threadIdx.x;          // 0..127
    const int tns = n >> 6;
    const int h   = n & 63;
    const float* W = (tns == 0) ? Wk : ((tns == 1) ? Wq : Wv);
    float v = W[(size_t)(kc * 128 + c) * H_ + h];
    if (tns == 1) v *= 0.125f;           // fold softmax scale into Q
    __nv_bfloat16 hi = __float2bfloat16_rn(v);
    __nv_bfloat16 lo = __float2bfloat16_rn(v - __bfloat162float(hi));
    const size_t off = (size_t)kc * W_CHUNK + (size_t)n * W_ROWB + (size_t)c * 2;
    *(__nv_bfloat16*)(g_wh + off) = hi;
    *(__nv_bfloat16*)(g_wl + off) = lo;
}

// ---------------------------------------------------------------------------
// Kernel 1: tensor-core QKV projection.
// Grid 512 (one 128-row x-tile each), block 256 (8 warps: 2(M) x 4(N)).
// ---------------------------------------------------------------------------
#define P_SA_H   64
#define P_SA_L   (P_SA_H + 128 * W_ROWB)          // A: 128x272B per half
#define P_SB_H   (P_SA_L + 128 * W_ROWB)
#define P_SB_L   (P_SB_H + W_CHUNK)
#define P_SMEM   (P_SB_L + W_CHUNK)               // 174 144 B

__global__ __launch_bounds__(256, 1) void qkv_mma_kernel(const float* __restrict__ x)
{
    extern __shared__ __align__(16) unsigned char sm[];
    const uint32_t sb = smem_u32(sm);

    const int tid = threadIdx.x;
    const int wid = tid >> 5;
    const int lid = tid & 31;
    const int g   = lid >> 2;
    const int t4  = lid & 3;
    const int wm  = wid >> 2;            // 0..1 : 64-row slab
    const int wn  = wid & 3;             // 0..3 : 48-col slab
    const int m0  = blockIdx.x * 128;    // global row base

    if (tid == 0) MBARRIER_INIT(sb, 1);
    __syncthreads();

    float O[4][6][4];
#pragma unroll
    for (int a = 0; a < 4; a++)
#pragma unroll
        for (int n = 0; n < 6; n++)
#pragma unroll
            for (int c = 0; c < 4; c++) O[a][n][c] = 0.0f;

    int ph = 0;
#pragma unroll 1
    for (int kc = 0; kc < 3; kc++) {
        __syncthreads();                 // prev chunk fully consumed
        if (tid == 0) {
            MBARRIER_EXPECT_TX(sb, 2 * W_CHUNK);
            BULK_G2S(sb + P_SB_H, g_wh + (size_t)kc * W_CHUNK, W_CHUNK, sb);
            BULK_G2S(sb + P_SB_L, g_wl + (size_t)kc * W_CHUNK, W_CHUNK, sb);
        }
        // stage A: x[m0..m0+127][kc*128..+127] -> split bf16 smem
        for (int it = 0; it < 16; it++) {
            const int idx = tid + it * 256;      // float4 index, 4096 total
            const int r   = idx >> 5;
            const int c4  = idx & 31;
            const float4 v = *(const float4*)(x + (size_t)(m0 + r) * C_ + kc * 128 + c4 * 4);
            uint32_t h0, l0, h1, l1;
            split2(v.x, v.y, h0, l0);
            split2(v.z, v.w, h1, l1);
            const uint32_t ba = (uint32_t)r * W_ROWB + (uint32_t)c4 * 8;
            *(uint32_t*)(sm + P_SA_H + ba)     = h0;
            *(uint32_t*)(sm + P_SA_H + ba + 4) = h1;
            *(uint32_t*)(sm + P_SA_L + ba)     = l0;
            *(uint32_t*)(sm + P_SA_L + ba + 4) = l1;
        }
        __syncthreads();
        MBARRIER_WAIT_PARITY(sb, ph); ph ^= 1;

#pragma unroll
        for (int ks = 0; ks < 8; ks++) {
            uint32_t Ah[4][4], Al[4][4];
#pragma unroll
            for (int mt = 0; mt < 4; mt++) {
                const uint32_t ra = (uint32_t)(wm * 64 + mt * 16 + (lid & 15)) * W_ROWB
                                  + (uint32_t)(ks * 32 + (lid >> 4) * 16);
                ldm_x4(Ah[mt], sb + P_SA_H + ra);
                ldm_x4(Al[mt], sb + P_SA_L + ra);
            }
#pragma unroll
            for (int np = 0; np < 3; np++) {
                uint32_t Bh[4], Bl[4];
                const uint32_t rb = (uint32_t)(wn * 48 + (np * 2 + (lid >> 4)) * 8 + (lid & 7)) * W_ROWB
                                  + (uint32_t)(ks * 32 + ((lid >> 3) & 1) * 16);
                ldm_x4(Bh, sb + P_SB_H + rb);
                ldm_x4(Bl, sb + P_SB_L + rb);
#pragma unroll
                for (int mt = 0; mt < 4; mt++) {
                    mma16816(O[mt][2 * np],     Ah[mt], Bh);
                    mma16816(O[mt][2 * np],     Ah[mt], Bl);
                    mma16816(O[mt][2 * np],     Al[mt], Bh);
                    mma16816(O[mt][2 * np + 1], Ah[mt], Bh + 2);
                    mma16816(O[mt][2 * np + 1], Ah[mt], Bl + 2);
                    mma16816(O[mt][2 * np + 1], Al[mt], Bh + 2);
                }
            }
        }
    }

    // ---- epilogue: route columns to split tile images ----
    const size_t imgoff = (size_t)blockIdx.x * QK_TILE;
#pragma unroll
    for (int nt = 0; nt < 6; nt++) {
        const int n   = wn * 48 + nt * 8 + 2 * t4;
        const int tns = n >> 6;
        const int h   = n & 63;
        unsigned char* ih = ((tns == 0) ? g_kh : (tns == 1) ? g_qh : g_vh) + imgoff;
        unsigned char* il = ((tns == 0) ? g_kl : (tns == 1) ? g_ql : g_vl) + imgoff;
#pragma unroll
        for (int mt = 0; mt < 4; mt++) {
            const int r0 = wm * 64 + mt * 16 + g;
            uint32_t hp, lp;
            split2(O[mt][nt][0], O[mt][nt][1], hp, lp);
            *(uint32_t*)(ih + (uint32_t)r0 * QK_ROWB + h * 2) = hp;
            *(uint32_t*)(il + (uint32_t)r0 * QK_ROWB + h * 2) = lp;
            split2(O[mt][nt][2], O[mt][nt][3], hp, lp);
            *(uint32_t*)(ih + (uint32_t)(r0 + 8) * QK_ROWB + h * 2) = hp;
            *(uint32_t*)(il + (uint32_t)(r0 + 8) * QK_ROWB + h * 2) = lp;
        }
    }
}

// ---------------------------------------------------------------------------
// Kernel 2: mma.sync bf16 causal flash attention.
// Grid 512 (b, qt), block 256 (8 warps x 16 query rows) -> 2 warps/SMSP.
// ---------------------------------------------------------------------------
#define SOFF_BAR 0
#define SOFF_QH  64
#define SOFF_QL  (SOFF_QH + QK_TILE)
#define SOFF_BUF (SOFF_QL + QK_TILE)
#define BUF_SZ   (4 * QK_TILE)             // KH, KL, VH, VL
#define SMEM_NEED (SOFF_BUF + 2 * BUF_SZ)  // 184 384

__global__ __launch_bounds__(256, 1) void attn_mma_kernel(float* __restrict__ out)
{
    extern __shared__ __align__(16) unsigned char sm[];
    const uint32_t sb = smem_u32(sm);

    const int tid = threadIdx.x;
    const int wid = tid >> 5;       // 0..7, warp handles rows wid*16..+15
    const int lid = tid & 31;
    const int g   = lid >> 2;
    const int t4  = lid & 3;
    const int b   = blockIdx.x >> 4;
    const int qt  = 15 - (blockIdx.x & 15);

    if (tid == 0) {
        MBARRIER_INIT(sb + SOFF_BAR, 1);
        MBARRIER_INIT(sb + SOFF_BAR + 8, 1);
    }
    __syncthreads();

    if (tid == 0) {
        const size_t qk = (size_t)(b * NTILE + qt);
        MBARRIER_EXPECT_TX(sb + SOFF_BAR, 2 * QK_TILE + BUF_SZ);
        BULK_G2S(sb + SOFF_QH, g_qh + qk * QK_TILE, QK_TILE, sb + SOFF_BAR);
        BULK_G2S(sb + SOFF_QL, g_ql + qk * QK_TILE, QK_TILE, sb + SOFF_BAR);
        BULK_G2S(sb + SOFF_BUF,                g_kh + qk * QK_TILE, QK_TILE, sb + SOFF_BAR);
        BULK_G2S(sb + SOFF_BUF + QK_TILE,      g_kl + qk * QK_TILE, QK_TILE, sb + SOFF_BAR);
        BULK_G2S(sb + SOFF_BUF + 2 * QK_TILE,  g_vh + qk * QK_TILE, QK_TILE, sb + SOFF_BAR);
        BULK_G2S(sb + SOFF_BUF + 3 * QK_TILE,  g_vl + qk * QK_TILE, QK_TILE, sb + SOFF_BAR);
    }

    float O[8][4];
#pragma unroll
    for (int n = 0; n < 8; n++)
#pragma unroll
        for (int c = 0; c < 4; c++) O[n][c] = 0.0f;

    float lsum[2] = {0.f, 0.f};
    float mrun[2] = {-1e30f, -1e30f};
    int ph0 = 0, ph1 = 0;

#pragma unroll 1
    for (int i = 0; i <= qt; i++) {
        const int kt  = qt - i;
        const int buf = i & 1;
        __syncthreads();
        if (i < qt && tid == 0) {
            const int ob = buf ^ 1;
            const size_t kk = (size_t)(b * NTILE + kt - 1);
            const uint32_t bb = sb + SOFF_BUF + ob * BUF_SZ;
            MBARRIER_EXPECT_TX(sb + SOFF_BAR + 8 * ob, BUF_SZ);
            BULK_G2S(bb,                g_kh + kk * QK_TILE, QK_TILE, sb + SOFF_BAR + 8 * ob);
            BULK_G2S(bb + QK_TILE,      g_kl + kk * QK_TILE, QK_TILE, sb + SOFF_BAR + 8 * ob);
            BULK_G2S(bb + 2 * QK_TILE,  g_vh + kk * QK_TILE, QK_TILE, sb + SOFF_BAR + 8 * ob);
            BULK_G2S(bb + 3 * QK_TILE,  g_vl + kk * QK_TILE, QK_TILE, sb + SOFF_BAR + 8 * ob);
        }
        if (buf == 0) { MBARRIER_WAIT_PARITY(sb + SOFF_BAR, ph0); ph0 ^= 1; }
        else          { MBARRIER_WAIT_PARITY(sb + SOFF_BAR + 8, ph1); ph1 ^= 1; }

        const uint32_t sKH = sb + SOFF_BUF + buf * BUF_SZ;
        const uint32_t sKL = sKH + QK_TILE;
        const uint32_t sVH = sKH + 2 * QK_TILE;
        const uint32_t sVL = sKH + 3 * QK_TILE;
        const bool diag = (i == 0);

#pragma unroll
        for (int ch = 0; ch < 4; ch++) {      // 32-key chunks
            float S[4][4];
#pragma unroll
            for (int n = 0; n < 4; n++)
#pragma unroll
                for (int c = 0; c < 4; c++) S[n][c] = 0.0f;

#pragma unroll
            for (int ks = 0; ks < 4; ks++) {  // 16-wide head chunks
                uint32_t aqh[4], aql[4];
                const uint32_t ra = (uint32_t)(wid * 16 + (lid & 15)) * QK_ROWB
                                  + (uint32_t)(ks * 32 + (lid >> 4) * 16);
                ldm_x4(aqh, sb + SOFF_QH + ra);
                ldm_x4(aql, sb + SOFF_QL + ra);
#pragma unroll
                for (int np = 0; np < 2; np++) {
                    uint32_t bh[4], bl[4];
                    const uint32_t rb = (uint32_t)(ch * 32 + (np * 2 + (lid >> 4)) * 8 + (lid & 7)) * QK_ROWB
                                      + (uint32_t)(ks * 32 + ((lid >> 3) & 1) * 16);
                    ldm_x4(bh, sKH + rb);
                    ldm_x4(bl, sKL + rb);
                    mma16816(S[2 * np],     aqh, bh);
                    mma16816(S[2 * np],     aqh, bl);
                    mma16816(S[2 * np],     aql, bh);
                    mma16816(S[2 * np + 1], aqh, bh + 2);
                    mma16816(S[2 * np + 1], aqh, bl + 2);
                    mma16816(S[2 * np + 1], aql, bh + 2);
                }
            }

            // ---- softmax (diag tile: mask + running-max update) ----
            if (diag) {
                const int r0 = wid * 16 + g;
                float cm0 = -1e30f, cm1 = -1e30f;
#pragma unroll
                for (int nt = 0; nt < 4; nt++) {
                    const int j0 = ch * 32 + nt * 8 + 2 * t4;
                    if (j0     > r0)     S[nt][0] = -1e30f;
                    if (j0 + 1 > r0)     S[nt][1] = -1e30f;
                    if (j0     > r0 + 8) S[nt][2] = -1e30f;
                    if (j0 + 1 > r0 + 8) S[nt][3] = -1e30f;
                    cm0 = fmaxf(cm0, fmaxf(S[nt][0], S[nt][1]));
                    cm1 = fmaxf(cm1, fmaxf(S[nt][2], S[nt][3]));
                }
                cm0 = fmaxf(cm0, __shfl_xor_sync(0xffffffffu, cm0, 1));
                cm0 = fmaxf(cm0, __shfl_xor_sync(0xffffffffu, cm0, 2));
                cm1 = fmaxf(cm1, __shfl_xor_sync(0xffffffffu, cm1, 1));
                cm1 = fmaxf(cm1, __shfl_xor_sync(0xffffffffu, cm1, 2));
                const float nm0 = fmaxf(mrun[0], cm0);
                const float nm1 = fmaxf(mrun[1], cm1);
                const float c0 = __expf(mrun[0] - nm0);
                const float c1 = __expf(mrun[1] - nm1);
                lsum[0] *= c0;
                lsum[1] *= c1;
#pragma unroll
                for (int n = 0; n < 8; n++) {
                    O[n][0] *= c0; O[n][1] *= c0;
                    O[n][2] *= c1; O[n][3] *= c1;
                }
                mrun[0] = nm0;
                mrun[1] = nm1;
            }
            {
                const float m0 = mrun[0], m1 = mrun[1];
                float s0 = 0.f, s1 = 0.f;
#pragma unroll
                for (int nt = 0; nt < 4; nt++) {
                    S[nt][0] = __expf(S[nt][0] - m0);
                    S[nt][1] = __expf(S[nt][1] - m0);
                    S[nt][2] = __expf(S[nt][2] - m1);
                    S[nt][3] = __expf(S[nt][3] - m1);
                    s0 += S[nt][0] + S[nt][1];
                    s1 += S[nt][2] + S[nt][3];
                }
                lsum[0] += s0;
                lsum[1] += s1;
            }

            // ---- O += P*V (P from registers; V via ldmatrix.trans) ----
#pragma unroll
            for (int kp = 0; kp < 2; kp++) {
                uint32_t aph[4], apl[4];
                split2(S[2 * kp][0],     S[2 * kp][1],     aph[0], apl[0]);
                split2(S[2 * kp][2],     S[2 * kp][3],     aph[1], apl[1]);
                split2(S[2 * kp + 1][0], S[2 * kp + 1][1], aph[2], apl[2]);
                split2(S[2 * kp + 1][2], S[2 * kp + 1][3], aph[3], apl[3]);
                const int k0 = ch * 32 + kp * 16;
#pragma unroll
                for (int np = 0; np < 4; np++) {
                    uint32_t vh[4], vl[4];
                    const uint32_t rv = (uint32_t)(k0 + (lid & 15)) * QK_ROWB
                                      + (uint32_t)((np * 2 + (lid >> 4)) * 16);
                    ldm_x4t(vh, sVH + rv);
                    ldm_x4t(vl, sVL + rv);
                    mma16816(O[2 * np],     aph, vh);
                    mma16816(O[2 * np],     aph, vl);
                    mma16816(O[2 * np],     apl, vh);
                    mma16816(O[2 * np + 1], aph, vh + 2);
                    mma16816(O[2 * np + 1], aph, vl + 2);
                    mma16816(O[2 * np + 1], apl, vh + 2);
                }
            }
        }
    }

    // ---- epilogue: normalize and store ----
#pragma unroll
    for (int hf = 0; hf < 2; hf++) {
        float l = lsum[hf];
        l += __shfl_xor_sync(0xffffffffu, l, 1);
        l += __shfl_xor_sync(0xffffffffu, l, 2);
        const float inv = 1.0f / l;
        const int row = qt * 128 + wid * 16 + g + hf * 8;
        float* orow = out + ((size_t)b * T_ + row) * H_;
#pragma unroll
        for (int nt = 0; nt < 8; nt++) {
            float2 v;
            v.x = O[nt][2 * hf]     * inv;
            v.y = O[nt][2 * hf + 1] * inv;
            *(float2*)(orow + nt * 8 + 2 * t4) = v;
        }
    }
}

// ---------------------------------------------------------------------------
extern "C" void kernel_launch(void* const* d_in, const int* in_sizes, int n_in,
                              void* d_out, int out_size)
{
    const float* x  = (const float*)d_in[0];
    const float* Wk = (const float*)d_in[1];
    const float* Wq = (const float*)d_in[2];
    const float* Wv = (const float*)d_in[3];
    float* out = (float*)d_out;

    cudaFuncSetAttribute(qkv_mma_kernel,
                         cudaFuncAttributeMaxDynamicSharedMemorySize, P_SMEM);
    cudaFuncSetAttribute(attn_mma_kernel,
                         cudaFuncAttributeMaxDynamicSharedMemorySize, SMEM_NEED);

    prep_w_kernel<<<dim3(192, 3), 128>>>(Wk, Wq, Wv);
    qkv_mma_kernel<<<512, 256, P_SMEM>>>(x);
    attn_mma_kernel<<<B_ * NTILE, 256, SMEM_NEED>>>(out);
}